// round 12
// baseline (speedup 1.0000x reference)
#include <cuda_runtime.h>
#include <cstdint>

// Problem geometry (fixed: GRID = (32,32,32), 6 channels)
#define NCELL 32768
#define CMASK 32767          // NCELL-1: power-of-two address clamp
#define NCH   6
#define NCTA  128            // all CTAs co-resident
#define NTHR  256            // one thread per cell
#define FLAG_STRIDE 64       // 256B apart -> distinct L2 slices
#define NV4   (NCH * NCELL / 4)
#define NREP  8              // replicated freeze words (16 CTAs read each)
#define FRZ_STRIDE 32        // 128B apart
#define FLAG_INF 0x7fffffffu // "exited" flag value: satisfies any wait

// Persistent device scratch (allocation-free). All sync state re-zeroed at the
// top of each launch, published by the one-time init barrier -> deterministic
// across calls / graph replays.
__device__ __align__(16) float g_po[2][NCH * NCELL];     // double-buffered po = clip(D·phi)
__device__ volatile unsigned g_flags[NCTA * FLAG_STRIDE];// per-CTA superstep counters
__device__ volatile unsigned g_freeze[NREP * FRZ_STRIDE];// write-once: tail_start (0 = none)
__device__ int      g_tail_start;
__device__ int      g_maxit;
// init-barrier state (classic; gen relative -> replay-safe without reset)
__device__ unsigned g_ib_arrive;
__device__ volatile unsigned g_ib_gen;

__device__ __forceinline__ float clip01(float a) {
    return fminf(fmaxf(a, 0.0f), 1.0f);
}

// Scoped release store: orders all prior (CTA-cumulative via bar.sync) writes
// before the flag becomes visible at gpu scope.
__device__ __forceinline__ void st_release_gpu(volatile unsigned* p, unsigned v) {
    asm volatile("st.release.gpu.global.u32 [%0], %1;"
                 :: "l"((unsigned*)p), "r"(v) : "memory");
}

// Classic atomic grid barrier — used ONCE per launch to publish init state.
__device__ __forceinline__ void init_grid_sync()
{
    __syncthreads();
    if (threadIdx.x == 0) {
        __threadfence();
        unsigned gen = g_ib_gen;
        unsigned old = atomicAdd(&g_ib_arrive, 1u);
        if (old == NCTA - 1) {
            atomicExch(&g_ib_arrive, 0u);
            __threadfence();
            g_ib_gen = gen + 1u;
        } else {
            while (g_ib_gen == gen) { }
        }
        __threadfence();
    }
    __syncthreads();
}

__global__ void __launch_bounds__(NTHR, 1)
flash_wave_kernel(const float* __restrict__ D,
                  const int* __restrict__ p_sx, const int* __restrict__ p_sy,
                  const int* __restrict__ p_sz, const int* __restrict__ p_ex,
                  const int* __restrict__ p_ey, const int* __restrict__ p_ez,
                  const int* __restrict__ p_mi,
                  float* __restrict__ out)
{
    __shared__ int   s_par[7];
    __shared__ int   s_fz[2];       // [0]: g_freeze echo, [1]: local (target CTA)
    __shared__ int   s_nb[12];      // neighbor CTA ids (halo distance <= 2)
    __shared__ int   s_nnb;
    __shared__ float s_probe[2];    // target-cell sums (target CTA only)

    const int bid = blockIdx.x;
    const int c   = bid * NTHR + threadIdx.x;   // this thread's cell

    if (threadIdx.x == 0) {
        s_par[0] = *p_sx; s_par[1] = *p_sy; s_par[2] = *p_sz;
        s_par[3] = *p_ex; s_par[4] = *p_ey; s_par[5] = *p_ez;
        s_par[6] = *p_mi;
        g_flags[bid * FLAG_STRIDE] = 0u;        // reset my superstep counter
        s_fz[1] = 0;

        // Neighbor CTA set: CTA = (X = bid>>2, Y-octant = bid&3), 8 y's, full z.
        // Distance-2 halo touches (X±2,Y), (X±1,Y+{-1,0,1}), (X,Y±1).
        const int X = bid >> 2, Y = bid & 3;
        const int off[10][2] = {{-2,0},{2,0},{-1,-1},{-1,0},{-1,1},
                                { 1,-1},{1,0},{ 1, 1},{ 0,-1},{0,1}};
        int n = 0;
        for (int i = 0; i < 10; i++) {
            int Xn = X + off[i][0], Yn = Y + off[i][1];
            if ((unsigned)Xn < 32u && (unsigned)Yn < 4u)
                s_nb[n++] = Xn * 4 + Yn;
        }
        s_nnb = n;
    }
    if (c < NREP) g_freeze[c * FRZ_STRIDE] = 0u;   // zero freeze replicas
    __syncthreads();

    const int srcc  = (s_par[0] << 10) + (s_par[1] << 5) + s_par[2];
    const int ct    = (s_par[3] << 10) + (s_par[4] << 5) + s_par[5];
    const int maxit = s_par[6];
    const int tgt_cta = ct >> 8;                // CTA owning the target cell

    if (c == 0) {
        g_maxit = maxit;
        g_tail_start = maxit;   // default: no tail (target CTA overwrites)
    }

    const int x = c >> 10;
    const int y = (c >> 5) & 31;
    const int z = c & 31;

    // Channel ch's SOURCE offset (gather form): flattened deltas.
    const int dx[6] = {-1, 1, 0, 0, 0, 0};
    const int dy[6] = { 0, 0,-1, 1, 0, 0};
    const int dz[6] = { 0, 0, 0, 0,-1, 1};
    const int doff[6] = {-1024, 1024, -32, 32, -1, 1};

    // Own active_D rows (36 regs): D[o][i][c] + 0.95
    float Dr[36];
    #pragma unroll
    for (int k = 0; k < 36; k++) Dr[k] = D[k * NCELL + c] + 0.95f;

    // Level-1 gather validity mask; addresses computed on the fly as
    // (c + doff) & CMASK (invalid gathers are value-gated to zero).
    float m1[6];
    #pragma unroll
    for (int ch = 0; ch < 6; ch++) {
        int x1 = x + dx[ch], y1 = y + dy[ch], z1 = z + dz[ch];
        bool ok = ((unsigned)x1 < 32u) & ((unsigned)y1 < 32u) & ((unsigned)z1 < 32u);
        m1[ch] = ok ? 1.0f : 0.0f;
    }

    // Neighbor-D rows with all boundary conditions folded in as zeros.
    float Dn[36];
    #pragma unroll
    for (int ch = 0; ch < 6; ch++) {
        int x1 = x + dx[ch], y1 = y + dy[ch], z1 = z + dz[ch];
        bool ok1 = ((unsigned)x1 < 32u) & ((unsigned)y1 < 32u) & ((unsigned)z1 < 32u);
        int s1i = ok1 ? ((x1 << 10) | (y1 << 5) | z1) : c;
        #pragma unroll
        for (int i = 0; i < 6; i++) {
            int x2 = x1 + dx[i], y2 = y1 + dy[i], z2 = z1 + dz[i];
            bool ok2 = ok1 & ((unsigned)x2 < 32u) & ((unsigned)y2 < 32u) & ((unsigned)z2 < 32u);
            Dn[ch * 6 + i] = ok2 ? (D[(ch * 6 + i) * NCELL + s1i] + 0.95f) : 0.0f;
        }
    }

    // Init: phi0 = zeros except all 6 channels = 1 at source; history[0] = phi0.
    const float v0 = (c == srcc) ? 1.0f : 0.0f;
    #pragma unroll
    for (int i = 0; i < 6; i++) __stcs(&out[i * NCELL + c], v0);

    // po(0) at own cell, kept in regs + stored to g_po[0].
    float po_reg[6];
    #pragma unroll
    for (int o = 0; o < 6; o++) {
        float a = Dr[o * 6] * v0;
        #pragma unroll
        for (int i = 1; i < 6; i++) a = fmaf(Dr[o * 6 + i], v0, a);
        po_reg[o] = clip01(a);
    }
    #pragma unroll
    for (int o = 0; o < 6; o++) g_po[0][o * NCELL + c] = po_reg[o];

    init_grid_sync();   // publish po(0) + zeroed flags/freeze grid-wide

    int t = 0;   // phi(t) = last committed state; history[0..t] written
    int p = 0;   // g_po[p] holds po(t)
    int k = 1;   // superstep counter (flag value)

    for (;;) {
        if (t + 1 >= maxit) break;

        const float* __restrict__ po_rd = g_po[p];

        // ---- v1 = phi(t+1): one gather per channel (L2, never stale) ----
        float v1[6];
        #pragma unroll
        for (int ch = 0; ch < 6; ch++)
            v1[ch] = m1[ch] * __ldcg(&po_rd[ch * NCELL + ((c + doff[ch]) & CMASK)]);

        if (t + 1 == maxit - 1) {
            float* h1 = out + (size_t)(t + 1) * (NCH * NCELL);
            #pragma unroll
            for (int ch = 0; ch < 6; ch++) __stcs(&h1[ch * NCELL + c], v1[ch]);
            break;
        }

        // ---- v2 = phi(t+2): recompute neighbors' po(t+1) from po(t) ----
        float v2[6];
        #pragma unroll
        for (int ch = 0; ch < 6; ch++) {
            float a = 0.0f;
            #pragma unroll
            for (int i = 0; i < 6; i++) {
                float g = (i == (ch ^ 1)) ? po_reg[i]
                        : __ldcg(&po_rd[i * NCELL + ((c + doff[ch] + doff[i]) & CMASK)]);
                if (i == 0) a = Dn[ch * 6] * g;
                else        a = fmaf(Dn[ch * 6 + i], g, a);
            }
            v2[ch] = clip01(a);
        }

        // Target thread publishes probe sums to ITS CTA's smem.
        if (c == ct) {
            s_probe[0] = v1[0] + v1[1] + v1[2] + v1[3] + v1[4] + v1[5];
            s_probe[1] = v2[0] + v2[1] + v2[2] + v2[3] + v2[4] + v2[5];
        }

        // po(t+2) at own cell -> other buffer (before flag publish).
        float po2[6];
        #pragma unroll
        for (int o = 0; o < 6; o++) {
            float a = Dr[o * 6] * v2[0];
            #pragma unroll
            for (int i = 1; i < 6; i++) a = fmaf(Dr[o * 6 + i], v2[i], a);
            po2[o] = clip01(a);
        }
        {
            float* __restrict__ po_wr = g_po[p ^ 1];
            #pragma unroll
            for (int o = 0; o < 6; o++) po_wr[o * NCELL + c] = po2[o];
        }

        // ---- Publish: local freeze detection (target CTA only) + flag = k ----
        __syncthreads();   // all po2 stores + s_probe done (CTA-cumulative)
        if (threadIdx.x == 0) {
            if (bid == tgt_cta && s_fz[1] == 0) {
                int fz = 0;
                if      (s_probe[0] > 0.01f) fz = t + 2;  // frozen phi = slab t+1
                else if (s_probe[1] > 0.01f) fz = t + 3;  // frozen phi = slab t+2
                if (fz) {
                    s_fz[1] = fz;                          // local, exact
                    g_tail_start = fz;
                    #pragma unroll
                    for (int r = 0; r < NREP; r++)         // write-once announce
                        g_freeze[r * FRZ_STRIDE] = (unsigned)fz;
                }
            }
            st_release_gpu(&g_flags[bid * FLAG_STRIDE], (unsigned)k);
        }

        // history[t+1] = v1 and SPECULATIVE history[t+2] = v2 — overlap with
        // the waits below. Slabs >= tail_start are overwritten by the tail
        // kernel, so speculation past the freeze point is safe.
        {
            float* h1 = out + (size_t)(t + 1) * (NCH * NCELL);
            float* h2 = out + (size_t)(t + 2) * (NCH * NCELL);
            #pragma unroll
            for (int ch = 0; ch < 6; ch++) __stcs(&h1[ch * NCELL + c], v1[ch]);
            #pragma unroll
            for (int ch = 0; ch < 6; ch++) __stcs(&h2[ch * NCELL + c], v2[ch]);
        }

        // ---- Wait: neighbor flags >= k ONLY (purely local dataflow).
        //      Freeze check is ONE non-spinning load of a replicated word.
        if (threadIdx.x < 32) {
            const int nn = s_nnb;
            if ((int)threadIdx.x < nn) {
                volatile unsigned* w = &g_flags[s_nb[threadIdx.x] * FLAG_STRIDE];
                while (*w < (unsigned)k) { }
            } else if (threadIdx.x == 30) {
                s_fz[0] = (int)g_freeze[(bid & (NREP - 1)) * FRZ_STRIDE];
            }
            __syncwarp();
        }
        __syncthreads();

        // Exit once freeze is known AND all history slabs < tail_start are
        // written by this CTA (we wrote up to t+2 this superstep).
        {
            int fz = s_fz[0] > s_fz[1] ? s_fz[0] : s_fz[1];
            if (fz != 0 && t + 2 >= fz - 1) break;
        }

        #pragma unroll
        for (int o = 0; o < 6; o++) po_reg[o] = po2[o];
        p ^= 1;
        t += 2;
        k += 1;
    }

    // Mark exited: any neighbor waiting on our flag proceeds immediately
    // (it reads our final, deterministic po data).
    if (threadIdx.x == 0)
        st_release_gpu(&g_flags[bid * FLAG_STRIDE], FLAG_INF);
}

// Tail fill: slabs [g_tail_start, g_maxit) all equal history slab
// (g_tail_start - 1), read directly from out. One load, many stores.
// Grid: x = 192 CTAs x 256 thr = 49152 threads (one per float4), y = 6 chunks.
__global__ void __launch_bounds__(256)
tail_fill_kernel(float* __restrict__ out)
{
    const int t0 = g_tail_start;
    const int mi = g_maxit;
    const int nslab = mi - t0;
    if (nslab <= 0) return;

    const int idx = blockIdx.x * blockDim.x + threadIdx.x;
    if (idx >= NV4) return;

    const float4* __restrict__ src4 =
        reinterpret_cast<const float4*>(out + (size_t)(t0 - 1) * (NCH * NCELL));
    const float4 val = __ldcg(&src4[idx]);
    float4* __restrict__ dst4 = reinterpret_cast<float4*>(out);

    const int per = (nslab + gridDim.y - 1) / gridDim.y;
    const int u0  = t0 + blockIdx.y * per;
    const int u1  = (u0 + per < mi) ? (u0 + per) : mi;
    for (int u = u0; u < u1; u++)
        __stcs(&dst4[(size_t)u * NV4 + idx], val);
}

extern "C" void kernel_launch(void* const* d_in, const int* in_sizes, int n_in,
                              void* d_out, int out_size)
{
    const float* D  = (const float*)d_in[0];
    const int*   sx = (const int*)d_in[1];
    const int*   sy = (const int*)d_in[2];
    const int*   sz = (const int*)d_in[3];
    const int*   ex = (const int*)d_in[4];
    const int*   ey = (const int*)d_in[5];
    const int*   ez = (const int*)d_in[6];
    const int*   mi = (const int*)d_in[7];

    flash_wave_kernel<<<NCTA, NTHR>>>(D, sx, sy, sz, ex, ey, ez, mi, (float*)d_out);
    tail_fill_kernel<<<dim3(192, 6), 256>>>((float*)d_out);
}

// round 13
// speedup vs baseline: 1.0183x; 1.0183x over previous
#include <cuda_runtime.h>
#include <cstdint>

// Problem geometry (fixed: GRID = (32,32,32), 6 channels)
#define NCELL 32768
#define CMASK 32767          // NCELL-1: power-of-two address clamp
#define NCH   6
#define NCTA  128            // all CTAs co-resident
#define NTHR  256            // one thread per cell; warp = one (x,y) row
#define NROW  1024           // 32*32 (x,y) rows = one flag per warp
#define WF_STRIDE 32         // 128B between warp flags -> distinct L2 slices
#define NV4   (NCH * NCELL / 4)
#define NREP  8              // replicated freeze words
#define FRZ_STRIDE 32        // 128B apart
#define FLAG_INF 0x7fffffffu // "exited": satisfies any wait

// Persistent device scratch (allocation-free). All sync state re-zeroed at the
// top of each launch, published by the one-time init barrier -> deterministic
// across calls / graph replays.
__device__ __align__(16) float g_po[2][NCH * NCELL];      // double-buffered po
__device__ volatile unsigned g_wflags[NROW * WF_STRIDE];  // per-ROW superstep counters
__device__ volatile unsigned g_freeze[NREP * FRZ_STRIDE]; // write-once tail_start (0=none)
__device__ int      g_tail_start;
__device__ int      g_maxit;
// init-barrier state (classic; gen relative -> replay-safe without reset)
__device__ unsigned g_ib_arrive;
__device__ volatile unsigned g_ib_gen;

__device__ __forceinline__ float clip01(float a) {
    return fminf(fmaxf(a, 0.0f), 1.0f);
}

__device__ __forceinline__ void st_release_gpu(volatile unsigned* p, unsigned v) {
    asm volatile("st.release.gpu.global.u32 [%0], %1;"
                 :: "l"((unsigned*)p), "r"(v) : "memory");
}
__device__ __forceinline__ unsigned ld_acquire_gpu(volatile unsigned* p) {
    unsigned v;
    asm volatile("ld.acquire.gpu.global.u32 %0, [%1];"
                 : "=r"(v) : "l"((unsigned*)p) : "memory");
    return v;
}

// Classic atomic grid barrier — used ONCE per launch to publish init state.
__device__ __forceinline__ void init_grid_sync()
{
    __syncthreads();
    if (threadIdx.x == 0) {
        __threadfence();
        unsigned gen = g_ib_gen;
        unsigned old = atomicAdd(&g_ib_arrive, 1u);
        if (old == NCTA - 1) {
            atomicExch(&g_ib_arrive, 0u);
            __threadfence();
            g_ib_gen = gen + 1u;
        } else {
            while (g_ib_gen == gen) { }
        }
        __threadfence();
    }
    __syncthreads();
}

__global__ void __launch_bounds__(NTHR, 1)
flash_wave_kernel(const float* __restrict__ D,
                  const int* __restrict__ p_sx, const int* __restrict__ p_sy,
                  const int* __restrict__ p_sz, const int* __restrict__ p_ex,
                  const int* __restrict__ p_ey, const int* __restrict__ p_ez,
                  const int* __restrict__ p_mi,
                  float* __restrict__ out)
{
    const int bid  = blockIdx.x;
    const int c    = bid * NTHR + threadIdx.x;   // this thread's cell
    const int lane = threadIdx.x & 31;
    const int row  = c >> 5;                     // (x*32 + y): warp's row id

    // Broadcast params (same address across threads -> L2 broadcast).
    const int sx = *p_sx, sy = *p_sy, sz = *p_sz;
    const int ex = *p_ex, ey = *p_ey, ez = *p_ez;
    const int maxit = *p_mi;
    const int srcc = (sx << 10) + (sy << 5) + sz;
    const int ct   = (ex << 10) + (ey << 5) + ez;

    // Reset sync state (published grid-wide by init_grid_sync below).
    if (lane == 0) g_wflags[row * WF_STRIDE] = 0u;
    if (c < NREP)  g_freeze[c * FRZ_STRIDE] = 0u;
    if (c == 0) { g_maxit = maxit; g_tail_start = maxit; }

    const int x = c >> 10;
    const int y = (c >> 5) & 31;
    const int z = c & 31;

    // Channel ch's SOURCE offset (gather form): flattened deltas.
    const int dx[6] = {-1, 1, 0, 0, 0, 0};
    const int dy[6] = { 0, 0,-1, 1, 0, 0};
    const int dz[6] = { 0, 0, 0, 0,-1, 1};
    const int doff[6] = {-1024, 1024, -32, 32, -1, 1};

    // Per-lane poll assignment: 12 neighbor-row offsets packed as nibbles
    // (value+2), lane l extracts its (dx,dy). dx: {-2,2,-1,-1,-1,1,1,1,0,0,0,0}
    // dy: {0,0,-1,0,1,-1,0,1,-2,-1,1,2}.
    const unsigned long long DXP = 0x0000222233311140ULL;
    const unsigned long long DYP = 0x0000431032132122ULL;
    const int pdx = (int)((DXP >> (4 * lane)) & 15ULL) - 2;
    const int pdy = (int)((DYP >> (4 * lane)) & 15ULL) - 2;
    const bool pollv = (lane < 12)
                     && ((unsigned)(x + pdx) < 32u) && ((unsigned)(y + pdy) < 32u);
    const int prow = (x + pdx) * 32 + (y + pdy);

    // Own active_D rows (36 regs): D[o][i][c] + 0.95
    float Dr[36];
    #pragma unroll
    for (int k = 0; k < 36; k++) Dr[k] = D[k * NCELL + c] + 0.95f;

    // Level-1 gather validity mask (addresses on the fly: (c+doff)&CMASK).
    float m1[6];
    #pragma unroll
    for (int ch = 0; ch < 6; ch++) {
        int x1 = x + dx[ch], y1 = y + dy[ch], z1 = z + dz[ch];
        bool ok = ((unsigned)x1 < 32u) & ((unsigned)y1 < 32u) & ((unsigned)z1 < 32u);
        m1[ch] = ok ? 1.0f : 0.0f;
    }

    // Neighbor-D rows, boundary conditions folded in as zeros.
    float Dn[36];
    #pragma unroll
    for (int ch = 0; ch < 6; ch++) {
        int x1 = x + dx[ch], y1 = y + dy[ch], z1 = z + dz[ch];
        bool ok1 = ((unsigned)x1 < 32u) & ((unsigned)y1 < 32u) & ((unsigned)z1 < 32u);
        int s1i = ok1 ? ((x1 << 10) | (y1 << 5) | z1) : c;
        #pragma unroll
        for (int i = 0; i < 6; i++) {
            int x2 = x1 + dx[i], y2 = y1 + dy[i], z2 = z1 + dz[i];
            bool ok2 = ok1 & ((unsigned)x2 < 32u) & ((unsigned)y2 < 32u) & ((unsigned)z2 < 32u);
            Dn[ch * 6 + i] = ok2 ? (D[(ch * 6 + i) * NCELL + s1i] + 0.95f) : 0.0f;
        }
    }

    // Init: phi0 = zeros except all 6 channels = 1 at source; history[0] = phi0.
    const float v0 = (c == srcc) ? 1.0f : 0.0f;
    #pragma unroll
    for (int i = 0; i < 6; i++) __stcs(&out[i * NCELL + c], v0);

    // po(0) at own cell, kept in regs + stored to g_po[0].
    float po_reg[6];
    #pragma unroll
    for (int o = 0; o < 6; o++) {
        float a = Dr[o * 6] * v0;
        #pragma unroll
        for (int i = 1; i < 6; i++) a = fmaf(Dr[o * 6 + i], v0, a);
        po_reg[o] = clip01(a);
    }
    #pragma unroll
    for (int o = 0; o < 6; o++) g_po[0][o * NCELL + c] = po_reg[o];

    init_grid_sync();   // publish po(0) + zeroed flags/freeze grid-wide

    bool fz_written = false;   // target thread: freeze word written once
    int t = 0;   // phi(t) = last committed state; history[0..t] written
    int p = 0;   // g_po[p] holds po(t)
    int k = 1;   // superstep counter (flag value)

    for (;;) {
        if (t + 1 >= maxit) break;

        const float* __restrict__ po_rd = g_po[p];

        // ---- v1 = phi(t+1): one gather per channel ----
        float v1[6];
        #pragma unroll
        for (int ch = 0; ch < 6; ch++)
            v1[ch] = m1[ch] * __ldcg(&po_rd[ch * NCELL + ((c + doff[ch]) & CMASK)]);

        if (t + 1 == maxit - 1) {
            float* h1 = out + (size_t)(t + 1) * (NCH * NCELL);
            #pragma unroll
            for (int ch = 0; ch < 6; ch++) __stcs(&h1[ch * NCELL + c], v1[ch]);
            break;   // uniform across all warps (same t, maxit)
        }

        // ---- v2 = phi(t+2): recompute neighbors' po(t+1) from po(t) ----
        float v2[6];
        #pragma unroll
        for (int ch = 0; ch < 6; ch++) {
            float a = 0.0f;
            #pragma unroll
            for (int i = 0; i < 6; i++) {
                float g = (i == (ch ^ 1)) ? po_reg[i]
                        : __ldcg(&po_rd[i * NCELL + ((c + doff[ch] + doff[i]) & CMASK)]);
                if (i == 0) a = Dn[ch * 6] * g;
                else        a = fmaf(Dn[ch * 6 + i], g, a);
            }
            v2[ch] = clip01(a);
        }

        // po(t+2) at own cell -> other buffer.
        float po2[6];
        #pragma unroll
        for (int o = 0; o < 6; o++) {
            float a = Dr[o * 6] * v2[0];
            #pragma unroll
            for (int i = 1; i < 6; i++) a = fmaf(Dr[o * 6 + i], v2[i], a);
            po2[o] = clip01(a);
        }
        {
            float* __restrict__ po_wr = g_po[p ^ 1];
            #pragma unroll
            for (int o = 0; o < 6; o++) po_wr[o * NCELL + c] = po2[o];
        }

        // Target THREAD detects freeze locally and write-onces the announce.
        if (c == ct && !fz_written) {
            float s1 = v1[0] + v1[1] + v1[2] + v1[3] + v1[4] + v1[5];
            float s2 = v2[0] + v2[1] + v2[2] + v2[3] + v2[4] + v2[5];
            int fz = (s1 > 0.01f) ? (t + 2) : ((s2 > 0.01f) ? (t + 3) : 0);
            if (fz) {
                fz_written = true;
                g_tail_start = fz;
                #pragma unroll
                for (int r = 0; r < NREP; r++)
                    g_freeze[r * FRZ_STRIDE] = (unsigned)fz;
            }
        }

        // ---- Per-warp publish: all lanes' po2 stores ordered before the
        //      release via syncwarp; one release store per warp.
        __syncwarp();
        if (lane == 0)
            st_release_gpu(&g_wflags[row * WF_STRIDE], (unsigned)k);

        // history[t+1] = v1 and SPECULATIVE history[t+2] = v2 — overlap with
        // the polls below. Slabs >= tail_start are overwritten by the tail
        // kernel, so speculation past the freeze point is safe.
        {
            float* h1 = out + (size_t)(t + 1) * (NCH * NCELL);
            float* h2 = out + (size_t)(t + 2) * (NCH * NCELL);
            #pragma unroll
            for (int ch = 0; ch < 6; ch++) __stcs(&h1[ch * NCELL + c], v1[ch]);
            #pragma unroll
            for (int ch = 0; ch < 6; ch++) __stcs(&h2[ch * NCELL + c], v2[ch]);
        }

        // ---- Per-warp wait: lanes 0-11 poll the <=12 producer-row flags in
        //      parallel; lane 30 reads the freeze word (non-spinning).
        int fzg = 0;
        if (pollv) {
            while (ld_acquire_gpu(&g_wflags[prow * WF_STRIDE]) < (unsigned)k) { }
        } else if (lane == 30) {
            fzg = (int)g_freeze[(row & (NREP - 1)) * FRZ_STRIDE];
        }
        __syncwarp();
        int fz = __shfl_sync(0xffffffffu, fzg, 30);

        // Exit once freeze is known AND all slabs < tail_start are written
        // (this superstep wrote up to t+2). Post-freeze stale supersteps only
        // ever produce slabs >= tail_start (overwritten by tail) — safe.
        if (fz != 0 && t + 2 >= fz - 1) break;

        #pragma unroll
        for (int o = 0; o < 6; o++) po_reg[o] = po2[o];
        p ^= 1;
        t += 2;
        k += 1;
    }

    // Mark exited: any consumer waiting on this row proceeds immediately
    // (it reads our final, already-released po data).
    __syncwarp();
    if (lane == 0)
        st_release_gpu(&g_wflags[row * WF_STRIDE], FLAG_INF);
}

// Tail fill: slabs [g_tail_start, g_maxit) all equal history slab
// (g_tail_start - 1), read directly from out. One load, many stores.
// Grid: x = 192 CTAs x 256 thr = 49152 threads (one per float4), y = 6 chunks.
__global__ void __launch_bounds__(256)
tail_fill_kernel(float* __restrict__ out)
{
    const int t0 = g_tail_start;
    const int mi = g_maxit;
    const int nslab = mi - t0;
    if (nslab <= 0) return;

    const int idx = blockIdx.x * blockDim.x + threadIdx.x;
    if (idx >= NV4) return;

    const float4* __restrict__ src4 =
        reinterpret_cast<const float4*>(out + (size_t)(t0 - 1) * (NCH * NCELL));
    const float4 val = __ldcg(&src4[idx]);
    float4* __restrict__ dst4 = reinterpret_cast<float4*>(out);

    const int per = (nslab + gridDim.y - 1) / gridDim.y;
    const int u0  = t0 + blockIdx.y * per;
    const int u1  = (u0 + per < mi) ? (u0 + per) : mi;
    for (int u = u0; u < u1; u++)
        __stcs(&dst4[(size_t)u * NV4 + idx], val);
}

extern "C" void kernel_launch(void* const* d_in, const int* in_sizes, int n_in,
                              void* d_out, int out_size)
{
    const float* D  = (const float*)d_in[0];
    const int*   sx = (const int*)d_in[1];
    const int*   sy = (const int*)d_in[2];
    const int*   sz = (const int*)d_in[3];
    const int*   ex = (const int*)d_in[4];
    const int*   ey = (const int*)d_in[5];
    const int*   ez = (const int*)d_in[6];
    const int*   mi = (const int*)d_in[7];

    flash_wave_kernel<<<NCTA, NTHR>>>(D, sx, sy, sz, ex, ey, ez, mi, (float*)d_out);
    tail_fill_kernel<<<dim3(192, 6), 256>>>((float*)d_out);
}

// round 14
// speedup vs baseline: 1.0635x; 1.0444x over previous
#include <cuda_runtime.h>
#include <cstdint>

// Problem geometry (fixed: GRID = (32,32,32), 6 channels)
#define NCELL 32768
#define CMASK 32767          // NCELL-1: power-of-two address clamp
#define NCH   6
#define NCTA  128            // all CTAs co-resident
#define NTHR  256            // one thread per cell; warp = one (x,y) row
#define NROW  1024           // 32*32 (x,y) rows = one flag per warp
#define WF_STRIDE 32         // 128B between warp flags -> distinct L2 slices
#define NV4   (NCH * NCELL / 4)
#define NREP  8              // replicated freeze words
#define FRZ_STRIDE 32        // 128B apart
#define FLAG_INF 0x7fffffffu // "exited": satisfies any wait
#define FULLMASK 0xffffffffu

// Persistent device scratch (allocation-free). All sync state re-zeroed at the
// top of each launch, published by the one-time init barrier -> deterministic
// across calls / graph replays.
__device__ __align__(16) float g_po[2][NCH * NCELL];      // double-buffered po
__device__ volatile unsigned g_wflags[NROW * WF_STRIDE];  // per-ROW superstep counters
__device__ volatile unsigned g_freeze[NREP * FRZ_STRIDE]; // write-once tail_start (0=none)
__device__ int      g_tail_start;
__device__ int      g_maxit;
// init-barrier state (classic; gen relative -> replay-safe without reset)
__device__ unsigned g_ib_arrive;
__device__ volatile unsigned g_ib_gen;

__device__ __forceinline__ float clip01(float a) {
    return fminf(fmaxf(a, 0.0f), 1.0f);
}

__device__ __forceinline__ void st_release_gpu(volatile unsigned* p, unsigned v) {
    asm volatile("st.release.gpu.global.u32 [%0], %1;"
                 :: "l"((unsigned*)p), "r"(v) : "memory");
}

// Classic atomic grid barrier — used ONCE per launch to publish init state.
__device__ __forceinline__ void init_grid_sync()
{
    __syncthreads();
    if (threadIdx.x == 0) {
        __threadfence();
        unsigned gen = g_ib_gen;
        unsigned old = atomicAdd(&g_ib_arrive, 1u);
        if (old == NCTA - 1) {
            atomicExch(&g_ib_arrive, 0u);
            __threadfence();
            g_ib_gen = gen + 1u;
        } else {
            while (g_ib_gen == gen) { }
        }
        __threadfence();
    }
    __syncthreads();
}

__global__ void __launch_bounds__(NTHR, 1)
flash_wave_kernel(const float* __restrict__ D,
                  const int* __restrict__ p_sx, const int* __restrict__ p_sy,
                  const int* __restrict__ p_sz, const int* __restrict__ p_ex,
                  const int* __restrict__ p_ey, const int* __restrict__ p_ez,
                  const int* __restrict__ p_mi,
                  float* __restrict__ out)
{
    const int bid  = blockIdx.x;
    const int c    = bid * NTHR + threadIdx.x;   // this thread's cell
    const int lane = threadIdx.x & 31;
    const int row  = c >> 5;                     // (x*32 + y): warp's row id

    // Broadcast params (same address across threads -> L2 broadcast).
    const int sx = *p_sx, sy = *p_sy, sz = *p_sz;
    const int ex = *p_ex, ey = *p_ey, ez = *p_ez;
    const int maxit = *p_mi;
    const int srcc = (sx << 10) + (sy << 5) + sz;
    const int ct   = (ex << 10) + (ey << 5) + ez;

    // Reset sync state (published grid-wide by init_grid_sync below).
    if (lane == 0) g_wflags[row * WF_STRIDE] = 0u;
    if (c < NREP)  g_freeze[c * FRZ_STRIDE] = 0u;
    if (c == 0) { g_maxit = maxit; g_tail_start = maxit; }

    const int x = c >> 10;
    const int y = (c >> 5) & 31;
    const int z = c & 31;

    // Channel ch's SOURCE offset (gather form): flattened deltas.
    const int dx[6] = {-1, 1, 0, 0, 0, 0};
    const int dy[6] = { 0, 0,-1, 1, 0, 0};
    const int dz[6] = { 0, 0, 0, 0,-1, 1};
    const int doff[6] = {-1024, 1024, -32, 32, -1, 1};

    // Per-lane poll assignment: 12 neighbor-row offsets packed as nibbles
    // (value+2). dx: {-2,2,-1,-1,-1,1,1,1,0,0,0,0}; dy: {0,0,-1,0,1,-1,0,1,-2,-1,1,2}.
    const unsigned long long DXP = 0x0000222233311140ULL;
    const unsigned long long DYP = 0x0000431032132122ULL;
    const int pdx = (int)((DXP >> (4 * lane)) & 15ULL) - 2;
    const int pdy = (int)((DYP >> (4 * lane)) & 15ULL) - 2;
    const bool pollv = (lane < 12)
                     && ((unsigned)(x + pdx) < 32u) && ((unsigned)(y + pdy) < 32u);
    const int prow = (x + pdx) * 32 + (y + pdy);

    // Own active_D rows (36 regs): D[o][i][c] + 0.95
    float Dr[36];
    #pragma unroll
    for (int k = 0; k < 36; k++) Dr[k] = D[k * NCELL + c] + 0.95f;

    // Level-1 gather validity mask (addresses on the fly: (c+doff)&CMASK).
    float m1[6];
    #pragma unroll
    for (int ch = 0; ch < 6; ch++) {
        int x1 = x + dx[ch], y1 = y + dy[ch], z1 = z + dz[ch];
        bool ok = ((unsigned)x1 < 32u) & ((unsigned)y1 < 32u) & ((unsigned)z1 < 32u);
        m1[ch] = ok ? 1.0f : 0.0f;
    }

    // Neighbor-D rows, boundary conditions folded in as zeros.
    float Dn[36];
    #pragma unroll
    for (int ch = 0; ch < 6; ch++) {
        int x1 = x + dx[ch], y1 = y + dy[ch], z1 = z + dz[ch];
        bool ok1 = ((unsigned)x1 < 32u) & ((unsigned)y1 < 32u) & ((unsigned)z1 < 32u);
        int s1i = ok1 ? ((x1 << 10) | (y1 << 5) | z1) : c;
        #pragma unroll
        for (int i = 0; i < 6; i++) {
            int x2 = x1 + dx[i], y2 = y1 + dy[i], z2 = z1 + dz[i];
            bool ok2 = ok1 & ((unsigned)x2 < 32u) & ((unsigned)y2 < 32u) & ((unsigned)z2 < 32u);
            Dn[ch * 6 + i] = ok2 ? (D[(ch * 6 + i) * NCELL + s1i] + 0.95f) : 0.0f;
        }
    }

    // Init: phi0 = zeros except all 6 channels = 1 at source; history[0] = phi0.
    const float v0 = (c == srcc) ? 1.0f : 0.0f;
    #pragma unroll
    for (int i = 0; i < 6; i++) __stcs(&out[i * NCELL + c], v0);

    // po(0) at own cell, kept in regs + stored to g_po[0].
    float po_reg[6];
    #pragma unroll
    for (int o = 0; o < 6; o++) {
        float a = Dr[o * 6] * v0;
        #pragma unroll
        for (int i = 1; i < 6; i++) a = fmaf(Dr[o * 6 + i], v0, a);
        po_reg[o] = clip01(a);
    }
    #pragma unroll
    for (int o = 0; o < 6; o++) g_po[0][o * NCELL + c] = po_reg[o];

    init_grid_sync();   // publish po(0) + zeroed flags/freeze grid-wide

    bool fz_written = false;   // target thread: freeze word written once
    int t = 0;   // phi(t) = last committed state; history[0..t] written
    int p = 0;   // g_po[p] holds po(t)
    int k = 1;   // superstep counter (flag value)

    for (;;) {
        if (t + 1 >= maxit) break;

        const float* __restrict__ po_rd = g_po[p];

        // ---- v1 = phi(t+1). x/y channels: L2 gather. z channels: the
        //      neighbor's po(t) is the adjacent LANE's register copy (same
        //      bits as memory) -> warp shuffle, no load.
        float v1[6];
        v1[0] = m1[0] * __ldcg(&po_rd[0 * NCELL + ((c - 1024) & CMASK)]);
        v1[1] = m1[1] * __ldcg(&po_rd[1 * NCELL + ((c + 1024) & CMASK)]);
        v1[2] = m1[2] * __ldcg(&po_rd[2 * NCELL + ((c - 32) & CMASK)]);
        v1[3] = m1[3] * __ldcg(&po_rd[3 * NCELL + ((c + 32) & CMASK)]);
        v1[4] = m1[4] * __shfl_up_sync(FULLMASK, po_reg[4], 1);
        v1[5] = m1[5] * __shfl_down_sync(FULLMASK, po_reg[5], 1);

        if (t + 1 == maxit - 1) {
            float* h1 = out + (size_t)(t + 1) * (NCH * NCELL);
            #pragma unroll
            for (int ch = 0; ch < 6; ch++) __stcs(&h1[ch * NCELL + c], v1[ch]);
            break;   // uniform across all warps (same t, maxit)
        }

        // ---- v2 = phi(t+2) = clip(Σ_i Dn[ch][i] · v1[i](c+doff_ch)).
        //      ch 0..3 (x/y): recompute from po(t) gathers (i==ch^1 -> register).
        //      ch 4,5 (z): the neighbor's v1 lives in the adjacent lane ->
        //      pure shuffles, zero loads (bitwise identical: masked terms are
        //      0-valued either way, the register term equals m1(=1)*po(own)).
        float v2[6];
        #pragma unroll
        for (int ch = 0; ch < 4; ch++) {
            float a = 0.0f;
            #pragma unroll
            for (int i = 0; i < 6; i++) {
                float g = (i == (ch ^ 1)) ? po_reg[i]
                        : __ldcg(&po_rd[i * NCELL + ((c + doff[ch] + doff[i]) & CMASK)]);
                if (i == 0) a = Dn[ch * 6] * g;
                else        a = fmaf(Dn[ch * 6 + i], g, a);
            }
            v2[ch] = clip01(a);
        }
        {
            float a4 = 0.0f, a5 = 0.0f;
            #pragma unroll
            for (int i = 0; i < 6; i++) {
                float gu = __shfl_up_sync(FULLMASK, v1[i], 1);
                float gd = __shfl_down_sync(FULLMASK, v1[i], 1);
                if (i == 0) { a4 = Dn[24] * gu;           a5 = Dn[30] * gd; }
                else        { a4 = fmaf(Dn[24 + i], gu, a4); a5 = fmaf(Dn[30 + i], gd, a5); }
            }
            v2[4] = clip01(a4);
            v2[5] = clip01(a5);
        }

        // po(t+2) at own cell -> other buffer.
        float po2[6];
        #pragma unroll
        for (int o = 0; o < 6; o++) {
            float a = Dr[o * 6] * v2[0];
            #pragma unroll
            for (int i = 1; i < 6; i++) a = fmaf(Dr[o * 6 + i], v2[i], a);
            po2[o] = clip01(a);
        }
        {
            float* __restrict__ po_wr = g_po[p ^ 1];
            #pragma unroll
            for (int o = 0; o < 6; o++) po_wr[o * NCELL + c] = po2[o];
        }

        // Target THREAD detects freeze locally and write-onces the announce.
        if (c == ct && !fz_written) {
            float s1 = v1[0] + v1[1] + v1[2] + v1[3] + v1[4] + v1[5];
            float s2 = v2[0] + v2[1] + v2[2] + v2[3] + v2[4] + v2[5];
            int fz = (s1 > 0.01f) ? (t + 2) : ((s2 > 0.01f) ? (t + 3) : 0);
            if (fz) {
                fz_written = true;
                g_tail_start = fz;
                #pragma unroll
                for (int r = 0; r < NREP; r++)
                    g_freeze[r * FRZ_STRIDE] = (unsigned)fz;
            }
        }

        // ---- Per-warp publish: all lanes' po2 stores ordered before the
        //      release via syncwarp; one release store per warp.
        __syncwarp();
        if (lane == 0)
            st_release_gpu(&g_wflags[row * WF_STRIDE], (unsigned)k);

        // history[t+1] = v1 and SPECULATIVE history[t+2] = v2 — overlap with
        // the polls below. Slabs >= tail_start are overwritten by the tail
        // kernel, so speculation past the freeze point is safe.
        {
            float* h1 = out + (size_t)(t + 1) * (NCH * NCELL);
            float* h2 = out + (size_t)(t + 2) * (NCH * NCELL);
            #pragma unroll
            for (int ch = 0; ch < 6; ch++) __stcs(&h1[ch * NCELL + c], v1[ch]);
            #pragma unroll
            for (int ch = 0; ch < 6; ch++) __stcs(&h2[ch * NCELL + c], v2[ch]);
        }

        // ---- Per-warp wait: lanes 0-11 poll the <=12 producer-row flags in
        //      parallel (plain volatile loads: in-order issue + the control
        //      dependency orders the next superstep's .cg gathers after the
        //      observed flag); lane 30 reads the freeze word (non-spinning).
        int fzg = 0;
        if (pollv) {
            volatile unsigned* w = &g_wflags[prow * WF_STRIDE];
            while (*w < (unsigned)k) { }
        } else if (lane == 30) {
            fzg = (int)g_freeze[(row & (NREP - 1)) * FRZ_STRIDE];
        }
        __syncwarp();
        int fz = __shfl_sync(FULLMASK, fzg, 30);

        // Exit once freeze is known AND all slabs < tail_start are written
        // (this superstep wrote up to t+2).
        if (fz != 0 && t + 2 >= fz - 1) break;

        #pragma unroll
        for (int o = 0; o < 6; o++) po_reg[o] = po2[o];
        p ^= 1;
        t += 2;
        k += 1;
    }

    // Mark exited: any consumer waiting on this row proceeds immediately
    // (it reads our final, already-released po data).
    __syncwarp();
    if (lane == 0)
        st_release_gpu(&g_wflags[row * WF_STRIDE], FLAG_INF);
}

// Tail fill: slabs [g_tail_start, g_maxit) all equal history slab
// (g_tail_start - 1), read directly from out. One load, many stores.
// Grid: x = 192 CTAs x 256 thr = 49152 threads (one per float4), y = 6 chunks.
__global__ void __launch_bounds__(256)
tail_fill_kernel(float* __restrict__ out)
{
    const int t0 = g_tail_start;
    const int mi = g_maxit;
    const int nslab = mi - t0;
    if (nslab <= 0) return;

    const int idx = blockIdx.x * blockDim.x + threadIdx.x;
    if (idx >= NV4) return;

    const float4* __restrict__ src4 =
        reinterpret_cast<const float4*>(out + (size_t)(t0 - 1) * (NCH * NCELL));
    const float4 val = __ldcg(&src4[idx]);
    float4* __restrict__ dst4 = reinterpret_cast<float4*>(out);

    const int per = (nslab + gridDim.y - 1) / gridDim.y;
    const int u0  = t0 + blockIdx.y * per;
    const int u1  = (u0 + per < mi) ? (u0 + per) : mi;
    for (int u = u0; u < u1; u++)
        __stcs(&dst4[(size_t)u * NV4 + idx], val);
}

extern "C" void kernel_launch(void* const* d_in, const int* in_sizes, int n_in,
                              void* d_out, int out_size)
{
    const float* D  = (const float*)d_in[0];
    const int*   sx = (const int*)d_in[1];
    const int*   sy = (const int*)d_in[2];
    const int*   sz = (const int*)d_in[3];
    const int*   ex = (const int*)d_in[4];
    const int*   ey = (const int*)d_in[5];
    const int*   ez = (const int*)d_in[6];
    const int*   mi = (const int*)d_in[7];

    flash_wave_kernel<<<NCTA, NTHR>>>(D, sx, sy, sz, ex, ey, ez, mi, (float*)d_out);
    tail_fill_kernel<<<dim3(192, 6), 256>>>((float*)d_out);
}